// round 1
// baseline (speedup 1.0000x reference)
#include <cuda_runtime.h>
#include <math.h>

// Problem dims
#define TT 256
#define BB 64
#define DD 768
#define RR 2048

// Scratch (device globals — no runtime allocation allowed)
// g_Z[t][r][b] : precomputed input projection + bias, fp32, 128 MB
// g_X[buf][r][b] : double-buffered reservoir state (transposed layout), 1 MB
__device__ float g_Z[(size_t)TT * RR * BB];
__device__ float g_X[2][RR * BB];

// ---- packed fp32x2 helpers (sm_103a FFMA2 path) ----
__device__ __forceinline__ unsigned long long pack2(float lo, float hi) {
    unsigned long long r;
    asm("mov.b64 %0, {%1, %2};" : "=l"(r) : "f"(lo), "f"(hi));
    return r;
}
__device__ __forceinline__ void fma2(unsigned long long& d, unsigned long long a,
                                     unsigned long long b) {
    asm("fma.rn.f32x2 %0, %1, %2, %0;" : "+l"(d) : "l"(a), "l"(b));
}
__device__ __forceinline__ float2 unpack2(unsigned long long v) {
    float2 f;
    asm("mov.b64 {%0, %1}, %2;" : "=f"(f.x), "=f"(f.y) : "l"(v));
    return f;
}

// ---------------------------------------------------------------------------
// Initialize state buffer: X0[r][b] = initial_state[r]
// ---------------------------------------------------------------------------
__global__ void init_state_kernel(const float* __restrict__ init) {
    int idx = blockIdx.x * blockDim.x + threadIdx.x;  // 0 .. RR*BB-1
    g_X[0][idx] = init[idx >> 6];
}

// ---------------------------------------------------------------------------
// Phase 1: Z[t][r][b] = bias[r] + sum_d emb[t][b][d] * w_in[r][d]
// Grid: (RR/32, TT), 256 threads. CTA tile: 32 r x 64 b, K over D in chunks of 64.
// Thread: rc = tid>>3 (32 rows), bq = (tid&7)*8 (8 batch cols), packed f32x2 FMA.
// ---------------------------------------------------------------------------
__global__ void __launch_bounds__(256)
input_proj_kernel(const float* __restrict__ emb,
                  const float* __restrict__ w_in,
                  const float* __restrict__ bias) {
    __shared__ __align__(16) float Us[64][68];  // [k][b], padded
    __shared__ __align__(8)  float Ws[32][66];  // [r][k], padded (even stride for float2)

    const int t   = blockIdx.y;
    const int r0  = blockIdx.x * 32;
    const int tid = threadIdx.x;
    const float* embt = emb + (size_t)t * BB * DD;

    unsigned long long acc[4] = {0ull, 0ull, 0ull, 0ull};  // 8 fp32 accumulators
    const int rc = tid >> 3;          // 0..31
    const int bq = (tid & 7) * 8;     // 0,8,...,56

    for (int kb = 0; kb < DD; kb += 64) {
        // load U chunk: Us[k][b] = emb[t][b][kb+k]   (coalesced over k)
#pragma unroll
        for (int i = 0; i < 16; i++) {
            int idx = tid + i * 256;          // 0..4095
            int b = idx >> 6, k = idx & 63;
            Us[k][b] = embt[b * DD + kb + k];
        }
        // load W chunk: Ws[r][k] = w_in[r0+r][kb+k]
#pragma unroll
        for (int i = 0; i < 8; i++) {
            int idx = tid + i * 256;          // 0..2047
            int r = idx >> 6, k = idx & 63;
            Ws[r][k] = w_in[(size_t)(r0 + r) * DD + kb + k];
        }
        __syncthreads();

#pragma unroll
        for (int k = 0; k < 64; k += 2) {
            float2 w2 = *(const float2*)&Ws[rc][k];
            unsigned long long wp0 = pack2(w2.x, w2.x);
            unsigned long long wp1 = pack2(w2.y, w2.y);
            ulonglong2 x0 = *(const ulonglong2*)&Us[k][bq];
            ulonglong2 x1 = *(const ulonglong2*)&Us[k][bq + 4];
            ulonglong2 y0 = *(const ulonglong2*)&Us[k + 1][bq];
            ulonglong2 y1 = *(const ulonglong2*)&Us[k + 1][bq + 4];
            fma2(acc[0], wp0, x0.x); fma2(acc[1], wp0, x0.y);
            fma2(acc[2], wp0, x1.x); fma2(acc[3], wp0, x1.y);
            fma2(acc[0], wp1, y0.x); fma2(acc[1], wp1, y0.y);
            fma2(acc[2], wp1, y1.x); fma2(acc[3], wp1, y1.y);
        }
        __syncthreads();
    }

    const float bz = bias[r0 + rc];
    float* z = g_Z + ((size_t)t * RR + (r0 + rc)) * BB + bq;
    float2 f;
    f = unpack2(acc[0]); z[0] = f.x + bz; z[1] = f.y + bz;
    f = unpack2(acc[1]); z[2] = f.x + bz; z[3] = f.y + bz;
    f = unpack2(acc[2]); z[4] = f.x + bz; z[5] = f.y + bz;
    f = unpack2(acc[3]); z[6] = f.x + bz; z[7] = f.y + bz;
}

// ---------------------------------------------------------------------------
// Phase 2 (per time step t): P = W_res @ X_t   (M=2048, N=64, K=2048)
//   x_new[r][b] = 0.5*x[r][b] + 0.5*tanh(P[r][b] + Z[t][r][b]); masked by lengths.
// Writes next state buffer and out[b][t][r].
// Grid: RR/16 = 128 CTAs, 256 threads. CTA tile 16 r x 64 b, K chunks of 64.
// Thread: rc = tid>>4 (16 rows), bq = (tid&15)*4 (4 batch cols).
// ---------------------------------------------------------------------------
__global__ void __launch_bounds__(256)
step_kernel(int t, const int* __restrict__ lengths,
            const float* __restrict__ w_res,
            float* __restrict__ out) {
    __shared__ __align__(16) float Xs[64][68];  // [k][b]
    __shared__ __align__(8)  float Ws[16][66];  // [r][k]

    const int r0  = blockIdx.x * 16;
    const int tid = threadIdx.x;
    const float* cur = g_X[t & 1];
    float* nxt = g_X[(t + 1) & 1];

    unsigned long long acc[2] = {0ull, 0ull};   // 4 fp32 accumulators
    const int rc = tid >> 4;          // 0..15
    const int bq = (tid & 15) * 4;    // 0,4,...,60

    for (int kb = 0; kb < RR; kb += 64) {
        // load X chunk: Xs[k][b] = cur[(kb+k)*BB + b]  (coalesced over b)
#pragma unroll
        for (int i = 0; i < 16; i++) {
            int idx = tid + i * 256;          // 0..4095
            int k = idx >> 6, b = idx & 63;
            Xs[k][b] = cur[(kb + k) * BB + b];
        }
        // load W chunk
#pragma unroll
        for (int i = 0; i < 4; i++) {
            int idx = tid + i * 256;          // 0..1023
            int r = idx >> 6, k = idx & 63;
            Ws[r][k] = w_res[(size_t)(r0 + r) * RR + kb + k];
        }
        __syncthreads();

#pragma unroll
        for (int k = 0; k < 64; k += 2) {
            float2 w2 = *(const float2*)&Ws[rc][k];
            unsigned long long wp0 = pack2(w2.x, w2.x);
            unsigned long long wp1 = pack2(w2.y, w2.y);
            ulonglong2 x0 = *(const ulonglong2*)&Xs[k][bq];
            ulonglong2 x1 = *(const ulonglong2*)&Xs[k + 1][bq];
            fma2(acc[0], wp0, x0.x); fma2(acc[1], wp0, x0.y);
            fma2(acc[0], wp1, x1.x); fma2(acc[1], wp1, x1.y);
        }
        __syncthreads();
    }

    // Epilogue: leaky integration + tanh + mask + stores
    const int r = r0 + rc;
    const float4 z4 = *(const float4*)(g_Z + ((size_t)t * RR + r) * BB + bq);
    const float4 xo = *(const float4*)&cur[r * BB + bq];
    const float2 lo = unpack2(acc[0]);
    const float2 hi = unpack2(acc[1]);

    float xn[4];
    xn[0] = 0.5f * xo.x + 0.5f * tanhf(lo.x + z4.x);
    xn[1] = 0.5f * xo.y + 0.5f * tanhf(lo.y + z4.y);
    xn[2] = 0.5f * xo.z + 0.5f * tanhf(hi.x + z4.z);
    xn[3] = 0.5f * xo.w + 0.5f * tanhf(hi.y + z4.w);

#pragma unroll
    for (int j = 0; j < 4; j++) {
        int b = bq + j;
        if (lengths[b] - t <= 0) xn[j] = 0.0f;
        out[((size_t)b * TT + t) * RR + r] = xn[j];
    }
    *(float4*)&nxt[r * BB + bq] = make_float4(xn[0], xn[1], xn[2], xn[3]);
}

// ---------------------------------------------------------------------------
extern "C" void kernel_launch(void* const* d_in, const int* in_sizes, int n_in,
                              void* d_out, int out_size) {
    const float* emb     = (const float*)d_in[0];  // [T, B, D] f32
    const int*   lengths = (const int*)  d_in[1];  // [B] i32
    const float* w_in    = (const float*)d_in[2];  // [R, D] f32
    const float* w_res   = (const float*)d_in[3];  // [R, R] f32
    const float* bias    = (const float*)d_in[4];  // [R] f32
    const float* init    = (const float*)d_in[5];  // [R] f32
    float* out = (float*)d_out;                    // [B, T, R] f32

    init_state_kernel<<<(RR * BB) / 256, 256>>>(init);
    input_proj_kernel<<<dim3(RR / 32, TT), 256>>>(emb, w_in, bias);
    for (int t = 0; t < TT; t++) {
        step_kernel<<<RR / 16, 256>>>(t, lengths, w_res, out);
    }
}

// round 2
// speedup vs baseline: 1.2881x; 1.2881x over previous
#include <cuda_runtime.h>
#include <math.h>
#include <stdint.h>

#define TT 256
#define BB 64
#define DD 768
#define RR 2048
#define KSPLIT 4
#define ROWF 68                 // padded row stride in floats (272B, 16B-aligned)
#define CHF (64 * ROWF)         // floats per chunk buffer
#define SMEM_BYTES (4 * CHF * 4)  // Ws0,Ws1,Xs0,Xs1

// ---- device globals (no runtime allocation) ----
__device__ float g_Z[(size_t)TT * BB * RR];   // [t][b][r] input projection + bias (128 MB)
__device__ float g_XT[BB * RR];               // state, [b][r] (k-major for GEMM)
__device__ float g_P[KSPLIT][BB * RR];        // split-K partials, [s][b][r]
__device__ unsigned int g_sync;

// ---- packed fp32x2 ----
__device__ __forceinline__ void fma2(unsigned long long& d, unsigned long long a,
                                     unsigned long long b) {
    asm("fma.rn.f32x2 %0, %1, %2, %0;" : "+l"(d) : "l"(a), "l"(b));
}
__device__ __forceinline__ float hsum2(unsigned long long v) {
    float lo, hi;
    asm("mov.b64 {%0, %1}, %2;" : "=f"(lo), "=f"(hi) : "l"(v));
    return lo + hi;
}

// ---- cp.async ----
__device__ __forceinline__ void cp_async16(void* smem_dst, const void* gsrc) {
    unsigned s = (unsigned)__cvta_generic_to_shared(smem_dst);
    asm volatile("cp.async.cg.shared.global [%0], [%1], 16;" :: "r"(s), "l"(gsrc));
}
__device__ __forceinline__ void cp_commit() {
    asm volatile("cp.async.commit_group;");
}
template <int N>
__device__ __forceinline__ void cp_wait() {
    asm volatile("cp.async.wait_group %0;" :: "n"(N));
}

// ---- grid-wide barrier (all 128 CTAs co-resident) ----
__device__ __forceinline__ void grid_sync(unsigned target) {
    __threadfence();
    __syncthreads();
    if (threadIdx.x == 0) {
        atomicAdd(&g_sync, 1u);
        while (*((volatile unsigned*)&g_sync) < target) {}
        __threadfence();   // CCTL.IVALL: drop stale L1 lines before cross-SM reads
    }
    __syncthreads();
}

// ---- shared micro-kernel: one 64-k chunk, 4r x 4b fragment, packed along k ----
__device__ __forceinline__ void mma_chunk(const float* __restrict__ Wsb,
                                          const float* __restrict__ Xsb,
                                          int rg, int bg,
                                          unsigned long long acc[4][4]) {
#pragma unroll
    for (int k = 0; k < 64; k += 4) {
        ulonglong2 w[4], x[4];
#pragma unroll
        for (int rr = 0; rr < 4; rr++)
            w[rr] = *(const ulonglong2*)(Wsb + (rg * 4 + rr) * ROWF + k);
#pragma unroll
        for (int bb = 0; bb < 4; bb++)
            x[bb] = *(const ulonglong2*)(Xsb + (bg * 4 + bb) * ROWF + k);
#pragma unroll
        for (int rr = 0; rr < 4; rr++)
#pragma unroll
            for (int bb = 0; bb < 4; bb++) {
                fma2(acc[rr][bb], w[rr].x, x[bb].x);
                fma2(acc[rr][bb], w[rr].y, x[bb].y);
            }
    }
}

// ---------------------------------------------------------------------------
// init: state + sync counter
// ---------------------------------------------------------------------------
__global__ void init_kernel(const float* __restrict__ init) {
    int idx = blockIdx.x * blockDim.x + threadIdx.x;   // 0 .. BB*RR-1
    g_XT[idx] = init[idx & (RR - 1)];
    if (idx == 0) g_sync = 0u;
}

// ---------------------------------------------------------------------------
// input projection: Z[t][b][r] = bias[r] + sum_d emb[t*64+b][d] * w_in[r][d]
// grid (32 r-blocks, 256 t-blocks), 256 threads, tile 64r x 64n, K=768
// ---------------------------------------------------------------------------
__global__ void __launch_bounds__(256)
proj_kernel(const float* __restrict__ emb,
            const float* __restrict__ w_in,
            const float* __restrict__ bias) {
    extern __shared__ float sm[];
    float* Ws[2] = { sm, sm + CHF };
    float* Xs[2] = { sm + 2 * CHF, sm + 3 * CHF };

    const int tid = threadIdx.x;
    const int r0 = blockIdx.x * 64;
    const int t  = blockIdx.y;
    const int bg = tid & 15, rg = tid >> 4;

    // per-thread load coords: 4 segments of 16B each for W and X per chunk
    const int lrow = tid >> 4;           // reuse: i = tid + j*256 -> row=(i>>4), seg=(i&15)
    const int lseg = tid & 15;

    unsigned long long acc[4][4] = {};

    const int NCH = DD / 64;  // 12
    // prologue: chunk 0
#pragma unroll
    for (int j = 0; j < 4; j++) {
        int row = lrow + j * 16, seg = lseg;
        cp_async16(Ws[0] + row * ROWF + seg * 4,
                   w_in + (size_t)(r0 + row) * DD + seg * 4);
        cp_async16(Xs[0] + row * ROWF + seg * 4,
                   emb + ((size_t)t * 64 + row) * DD + seg * 4);
    }
    cp_commit();

    int buf = 0;
    for (int c = 0; c < NCH; c++) {
        if (c + 1 < NCH) {
            int kb = (c + 1) * 64;
#pragma unroll
            for (int j = 0; j < 4; j++) {
                int row = lrow + j * 16, seg = lseg;
                cp_async16(Ws[buf ^ 1] + row * ROWF + seg * 4,
                           w_in + (size_t)(r0 + row) * DD + kb + seg * 4);
                cp_async16(Xs[buf ^ 1] + row * ROWF + seg * 4,
                           emb + ((size_t)t * 64 + row) * DD + kb + seg * 4);
            }
            cp_commit();
            cp_wait<1>();
        } else {
            cp_wait<0>();
        }
        __syncthreads();
        mma_chunk(Ws[buf], Xs[buf], rg, bg, acc);
        __syncthreads();
        buf ^= 1;
    }

    float bz[4];
#pragma unroll
    for (int rr = 0; rr < 4; rr++) bz[rr] = bias[r0 + rg * 4 + rr];

#pragma unroll
    for (int bb = 0; bb < 4; bb++) {
        float4 z;
        z.x = hsum2(acc[0][bb]) + bz[0];
        z.y = hsum2(acc[1][bb]) + bz[1];
        z.z = hsum2(acc[2][bb]) + bz[2];
        z.w = hsum2(acc[3][bb]) + bz[3];
        int b = bg * 4 + bb;
        *(float4*)&g_Z[((size_t)t * BB + b) * RR + r0 + rg * 4] = z;
    }
}

// ---------------------------------------------------------------------------
// persistent recurrence: 256 steps, 128 CTAs (32 r-blocks x 4 k-splits)
// ---------------------------------------------------------------------------
__global__ void __launch_bounds__(256)
esn_kernel(const int* __restrict__ lengths,
           const float* __restrict__ w_res,
           float* __restrict__ out) {
    extern __shared__ float sm[];
    float* Ws[2] = { sm, sm + CHF };
    float* Xs[2] = { sm + 2 * CHF, sm + 3 * CHF };

    const int tid = threadIdx.x;
    const int rb = blockIdx.x >> 2;      // 0..31
    const int ks = blockIdx.x & 3;       // 0..3
    const int r0 = rb * 64;
    const int k0 = ks * (RR / KSPLIT);   // 0,512,1024,1536
    const int bg = tid & 15, rg = tid >> 4;
    const int lrow = tid >> 4, lseg = tid & 15;

    // reduce-phase coords (each thread owns 4 r-contiguous elems of [b][r])
    const int ridx = blockIdx.x * 1024 + tid * 4;
    const int rb_b = ridx >> 11;               // batch index
    const int rlen = lengths[rb_b];

    unsigned phase = 0;

    for (int t = 0; t < TT; t++) {
        // ---------------- split-K GEMM partial: P[ks][b][r] ----------------
        unsigned long long acc[4][4] = {};
        const int NCH = (RR / KSPLIT) / 64;  // 8

#pragma unroll
        for (int j = 0; j < 4; j++) {
            int row = lrow + j * 16, seg = lseg;
            cp_async16(Ws[0] + row * ROWF + seg * 4,
                       w_res + (size_t)(r0 + row) * RR + k0 + seg * 4);
            cp_async16(Xs[0] + row * ROWF + seg * 4,
                       g_XT + row * RR + k0 + seg * 4);
        }
        cp_commit();

        int buf = 0;
        for (int c = 0; c < NCH; c++) {
            if (c + 1 < NCH) {
                int kb = k0 + (c + 1) * 64;
#pragma unroll
                for (int j = 0; j < 4; j++) {
                    int row = lrow + j * 16, seg = lseg;
                    cp_async16(Ws[buf ^ 1] + row * ROWF + seg * 4,
                               w_res + (size_t)(r0 + row) * RR + kb + seg * 4);
                    cp_async16(Xs[buf ^ 1] + row * ROWF + seg * 4,
                               g_XT + row * RR + kb + seg * 4);
                }
                cp_commit();
                cp_wait<1>();
            } else {
                cp_wait<0>();
            }
            __syncthreads();
            mma_chunk(Ws[buf], Xs[buf], rg, bg, acc);
            __syncthreads();
            buf ^= 1;
        }

#pragma unroll
        for (int bb = 0; bb < 4; bb++) {
            float4 p;
            p.x = hsum2(acc[0][bb]);
            p.y = hsum2(acc[1][bb]);
            p.z = hsum2(acc[2][bb]);
            p.w = hsum2(acc[3][bb]);
            int b = bg * 4 + bb;
            *(float4*)&g_P[ks][b * RR + r0 + rg * 4] = p;
        }

        grid_sync(128u * (++phase));

        // ---------------- reduce + leaky tanh epilogue (all coalesced) -----
        {
            float4 s0 = *(const float4*)&g_P[0][ridx];
            float4 s1 = *(const float4*)&g_P[1][ridx];
            float4 s2 = *(const float4*)&g_P[2][ridx];
            float4 s3 = *(const float4*)&g_P[3][ridx];
            float4 z  = *(const float4*)&g_Z[(size_t)t * (BB * RR) + ridx];
            float4 xo = *(const float4*)&g_XT[ridx];

            float m = (t < rlen) ? 0.5f : 0.0f;
            float4 xn;
            xn.x = m * (xo.x + tanhf(s0.x + s1.x + s2.x + s3.x + z.x));
            xn.y = m * (xo.y + tanhf(s0.y + s1.y + s2.y + s3.y + z.y));
            xn.z = m * (xo.z + tanhf(s0.z + s1.z + s2.z + s3.z + z.z));
            xn.w = m * (xo.w + tanhf(s0.w + s1.w + s2.w + s3.w + z.w));

            *(float4*)&g_XT[ridx] = xn;
            *(float4*)&out[((size_t)rb_b * TT + t) * RR + (ridx & (RR - 1))] = xn;
        }

        grid_sync(128u * (++phase));
    }
}

// ---------------------------------------------------------------------------
extern "C" void kernel_launch(void* const* d_in, const int* in_sizes, int n_in,
                              void* d_out, int out_size) {
    const float* emb     = (const float*)d_in[0];  // [T, B, D]
    const int*   lengths = (const int*)  d_in[1];  // [B]
    const float* w_in    = (const float*)d_in[2];  // [R, D]
    const float* w_res   = (const float*)d_in[3];  // [R, R]
    const float* bias    = (const float*)d_in[4];  // [R]
    const float* init    = (const float*)d_in[5];  // [R]
    float* out = (float*)d_out;                    // [B, T, R]

    cudaFuncSetAttribute(proj_kernel, cudaFuncAttributeMaxDynamicSharedMemorySize, SMEM_BYTES);
    cudaFuncSetAttribute(esn_kernel,  cudaFuncAttributeMaxDynamicSharedMemorySize, SMEM_BYTES);

    init_kernel<<<(BB * RR) / 256, 256>>>(init);
    proj_kernel<<<dim3(RR / 64, TT), 256, SMEM_BYTES>>>(emb, w_in, bias);
    esn_kernel<<<128, 256, SMEM_BYTES>>>(lengths, w_res, out);
}

// round 5
// speedup vs baseline: 2.3118x; 1.7947x over previous
#include <cuda_runtime.h>
#include <math.h>
#include <stdint.h>

#define TT 256
#define BB 64
#define DD 768
#define RR 2048
#define KSPLIT 4
#define ROWF 68                 // padded row stride in floats
#define CHF (64 * ROWF)
#define SMEM_BYTES (4 * CHF * 4)

// ---- device globals ----
__device__ float g_Z[(size_t)TT * BB * RR];   // [t][b][r]
__device__ float g_XT[BB * RR];               // state [b][r]
__device__ float g_P[KSPLIT][BB * RR];        // split-K partials [s][b][r]
__device__ unsigned int g_flag[128 * 8];      // per-CTA barrier flags (32B padded)

// ---- packed fp32x2 ----
__device__ __forceinline__ void fma2(unsigned long long& d, unsigned long long a,
                                     unsigned long long b) {
    asm("fma.rn.f32x2 %0, %1, %2, %0;" : "+l"(d) : "l"(a), "l"(b));
}
__device__ __forceinline__ float hsum2(unsigned long long v) {
    float lo, hi;
    asm("mov.b64 {%0, %1}, %2;" : "=f"(lo), "=f"(hi) : "l"(v));
    return lo + hi;
}

// ---- cp.async ----
__device__ __forceinline__ void cp_async16(void* smem_dst, const void* gsrc) {
    unsigned s = (unsigned)__cvta_generic_to_shared(smem_dst);
    asm volatile("cp.async.cg.shared.global [%0], [%1], 16;" :: "r"(s), "l"(gsrc));
}
__device__ __forceinline__ void cp_commit() { asm volatile("cp.async.commit_group;"); }
template <int N>
__device__ __forceinline__ void cp_wait() {
    asm volatile("cp.async.wait_group %0;" :: "n"(N));
}

// ---- streaming load (evict-first: keep Z out of L2's hot set) ----
__device__ __forceinline__ float4 ldcs4(const float4* p) {
    float4 v;
    asm volatile("ld.global.cs.v4.f32 {%0,%1,%2,%3}, [%4];"
                 : "=f"(v.x), "=f"(v.y), "=f"(v.z), "=f"(v.w) : "l"(p));
    return v;
}

// ---- flag-array grid barrier (128 co-resident CTAs) ----
__device__ __forceinline__ void grid_sync(unsigned phase) {
    __threadfence();
    __syncthreads();
    if (threadIdx.x == 0)
        ((volatile unsigned*)g_flag)[blockIdx.x * 8] = phase;
    if (threadIdx.x < 128) {
        while (((volatile unsigned*)g_flag)[threadIdx.x * 8] < phase) {}
    }
    __threadfence();
    __syncthreads();
}

// ---- micro-kernel: one 64-k chunk, 4r x 4b strided fragment (conflict-free) --
// Warp (rg=tid&15, bg=tid>>4): W rows rr*16+rg -> 16 distinct rows, stride 68
//   -> bank start (rg*4)&31: 2-way max. X rows bb*16+bg -> 2 distinct rows in a
//   warp -> broadcast. ~12 crossbar phases per warp-k4 vs 16 fma SMSP-cycles.
__device__ __forceinline__ void mma_chunk(const float* __restrict__ Wsb,
                                          const float* __restrict__ Xsb,
                                          int rg, int bg,
                                          unsigned long long acc[4][4]) {
#pragma unroll
    for (int k = 0; k < 64; k += 4) {
        ulonglong2 w[4], x[4];
#pragma unroll
        for (int rr = 0; rr < 4; rr++)
            w[rr] = *(const ulonglong2*)(Wsb + (rr * 16 + rg) * ROWF + k);
#pragma unroll
        for (int bb = 0; bb < 4; bb++)
            x[bb] = *(const ulonglong2*)(Xsb + (bb * 16 + bg) * ROWF + k);
#pragma unroll
        for (int rr = 0; rr < 4; rr++)
#pragma unroll
            for (int bb = 0; bb < 4; bb++) {
                fma2(acc[rr][bb], w[rr].x, x[bb].x);
                fma2(acc[rr][bb], w[rr].y, x[bb].y);
            }
    }
}

// ---------------------------------------------------------------------------
__global__ void init_kernel(const float* __restrict__ init) {
    int idx = blockIdx.x * blockDim.x + threadIdx.x;   // 0 .. BB*RR-1
    g_XT[idx] = init[idx & (RR - 1)];
    if (idx < 128 * 8) g_flag[idx] = 0u;
}

// ---------------------------------------------------------------------------
// proj: Z[t][b][r] = bias[r] + sum_d emb[t][b][d] * w_in[r][d]
// grid (32, 256), 256 thr, tile 64r x 64b, K=768
// ---------------------------------------------------------------------------
__global__ void __launch_bounds__(256)
proj_kernel(const float* __restrict__ emb,
            const float* __restrict__ w_in,
            const float* __restrict__ bias) {
    extern __shared__ float sm[];
    float* Ws[2] = { sm, sm + CHF };
    float* Xs[2] = { sm + 2 * CHF, sm + 3 * CHF };

    const int tid = threadIdx.x;
    const int r0 = blockIdx.x * 64;
    const int t  = blockIdx.y;
    const int rg = tid & 15, bg = tid >> 4;
    const int lrow = tid >> 4, lseg = tid & 15;

    unsigned long long acc[4][4] = {};
    const int NCH = DD / 64;  // 12

#pragma unroll
    for (int j = 0; j < 4; j++) {
        int row = lrow + j * 16;
        cp_async16(Ws[0] + row * ROWF + lseg * 4,
                   w_in + (size_t)(r0 + row) * DD + lseg * 4);
        cp_async16(Xs[0] + row * ROWF + lseg * 4,
                   emb + ((size_t)t * 64 + row) * DD + lseg * 4);
    }
    cp_commit();

    int buf = 0;
    for (int c = 0; c < NCH; c++) {
        if (c + 1 < NCH) {
            int kb = (c + 1) * 64;
#pragma unroll
            for (int j = 0; j < 4; j++) {
                int row = lrow + j * 16;
                cp_async16(Ws[buf ^ 1] + row * ROWF + lseg * 4,
                           w_in + (size_t)(r0 + row) * DD + kb + lseg * 4);
                cp_async16(Xs[buf ^ 1] + row * ROWF + lseg * 4,
                           emb + ((size_t)t * 64 + row) * DD + kb + lseg * 4);
            }
            cp_commit();
            cp_wait<1>();
        } else {
            cp_wait<0>();
        }
        __syncthreads();
        mma_chunk(Ws[buf], Xs[buf], rg, bg, acc);
        __syncthreads();
        buf ^= 1;
    }

    float bz[4];
#pragma unroll
    for (int rr = 0; rr < 4; rr++) bz[rr] = bias[r0 + rr * 16 + rg];

#pragma unroll
    for (int bb = 0; bb < 4; bb++) {
        int b = bb * 16 + bg;
        float* z = &g_Z[((size_t)t * BB + b) * RR + r0 + rg];
#pragma unroll
        for (int rr = 0; rr < 4; rr++)
            z[rr * 16] = hsum2(acc[rr][bb]) + bz[rr];
    }
}

// ---------------------------------------------------------------------------
// persistent recurrence: 128 CTAs (32 r-blocks x 4 k-splits), 256 steps
// ---------------------------------------------------------------------------
__global__ void __launch_bounds__(256)
esn_kernel(const int* __restrict__ lengths,
           const float* __restrict__ w_res,
           float* __restrict__ out) {
    extern __shared__ float sm[];
    float* Ws[2] = { sm, sm + CHF };
    float* Xs[2] = { sm + 2 * CHF, sm + 3 * CHF };

    const int tid = threadIdx.x;
    const int rb = blockIdx.x >> 2;
    const int ks = blockIdx.x & 3;
    const int r0 = rb * 64;
    const int k0 = ks * (RR / KSPLIT);
    const int rg = tid & 15, bg = tid >> 4;
    const int lrow = tid >> 4, lseg = tid & 15;

    const int ridx = blockIdx.x * 1024 + tid * 4;   // reduce-phase ownership
    const int rb_b = ridx >> 11;
    const int rlen = lengths[rb_b];

    unsigned phase = 0;

    for (int t = 0; t < TT; t++) {
        // ---------------- split-K GEMM partial ----------------
        unsigned long long acc[4][4] = {};
        const int NCH = (RR / KSPLIT) / 64;  // 8

#pragma unroll
        for (int j = 0; j < 4; j++) {
            int row = lrow + j * 16;
            cp_async16(Ws[0] + row * ROWF + lseg * 4,
                       w_res + (size_t)(r0 + row) * RR + k0 + lseg * 4);
            cp_async16(Xs[0] + row * ROWF + lseg * 4,
                       g_XT + row * RR + k0 + lseg * 4);
        }
        cp_commit();

        int buf = 0;
        for (int c = 0; c < NCH; c++) {
            if (c + 1 < NCH) {
                int kb = k0 + (c + 1) * 64;
#pragma unroll
                for (int j = 0; j < 4; j++) {
                    int row = lrow + j * 16;
                    cp_async16(Ws[buf ^ 1] + row * ROWF + lseg * 4,
                               w_res + (size_t)(r0 + row) * RR + kb + lseg * 4);
                    cp_async16(Xs[buf ^ 1] + row * ROWF + lseg * 4,
                               g_XT + row * RR + kb + lseg * 4);
                }
                cp_commit();
                cp_wait<1>();
            } else {
                cp_wait<0>();
            }
            __syncthreads();
            mma_chunk(Ws[buf], Xs[buf], rg, bg, acc);
            __syncthreads();
            buf ^= 1;
        }

        // store partials: scalar but sector-coalesced (16 consecutive r per half-warp)
#pragma unroll
        for (int bb = 0; bb < 4; bb++) {
            int b = bb * 16 + bg;
            float* p = &g_P[ks][b * RR + r0 + rg];
#pragma unroll
            for (int rr = 0; rr < 4; rr++)
                p[rr * 16] = hsum2(acc[rr][bb]);
        }

        grid_sync(++phase);

        // ---------------- reduce + leaky tanh epilogue ----------------
        {
            float4 s0 = *(const float4*)&g_P[0][ridx];
            float4 s1 = *(const float4*)&g_P[1][ridx];
            float4 s2 = *(const float4*)&g_P[2][ridx];
            float4 s3 = *(const float4*)&g_P[3][ridx];
            float4 z  = ldcs4((const float4*)&g_Z[(size_t)t * (BB * RR) + ridx]);
            float4 xo = *(const float4*)&g_XT[ridx];

            float m = (t < rlen) ? 0.5f : 0.0f;
            float4 xn;
            xn.x = m * (xo.x + tanhf(s0.x + s1.x + s2.x + s3.x + z.x));
            xn.y = m * (xo.y + tanhf(s0.y + s1.y + s2.y + s3.y + z.y));
            xn.z = m * (xo.z + tanhf(s0.z + s1.z + s2.z + s3.z + z.z));
            xn.w = m * (xo.w + tanhf(s0.w + s1.w + s2.w + s3.w + z.w));

            *(float4*)&g_XT[ridx] = xn;
            *(float4*)&out[((size_t)rb_b * TT + t) * RR + (ridx & (RR - 1))] = xn;
        }

        grid_sync(++phase);
    }
}

// ---------------------------------------------------------------------------
extern "C" void kernel_launch(void* const* d_in, const int* in_sizes, int n_in,
                              void* d_out, int out_size) {
    const float* emb     = (const float*)d_in[0];
    const int*   lengths = (const int*)  d_in[1];
    const float* w_in    = (const float*)d_in[2];
    const float* w_res   = (const float*)d_in[3];
    const float* bias    = (const float*)d_in[4];
    const float* init    = (const float*)d_in[5];
    float* out = (float*)d_out;

    cudaFuncSetAttribute(proj_kernel, cudaFuncAttributeMaxDynamicSharedMemorySize, SMEM_BYTES);
    cudaFuncSetAttribute(esn_kernel,  cudaFuncAttributeMaxDynamicSharedMemorySize, SMEM_BYTES);

    init_kernel<<<(BB * RR) / 256, 256>>>(init);
    proj_kernel<<<dim3(RR / 64, TT), 256, SMEM_BYTES>>>(emb, w_in, bias);
    esn_kernel<<<128, 256, SMEM_BYTES>>>(lengths, w_res, out);
}

// round 11
// speedup vs baseline: 3.6298x; 1.5701x over previous
#include <cuda_runtime.h>
#include <cuda_bf16.h>
#include <math.h>
#include <stdint.h>

#define TT 256
#define BB 64
#define DD 768
#define RR 2048
#define KSPLIT 8
#define KS (RR / KSPLIT)          // 256 k per CTA

// ---- proj tiling (fp32 SIMT, validated) ----
#define ROWF 68
#define CHF (64 * ROWF)
#define PROJ_SMEM (4 * CHF * 4)

// ---- esn smem layout (bytes). bf16 rows padded to 528B (264 halves) ----
#define PITCHB 528
#define OFF_WHI  0
#define OFF_WLO  (128 * PITCHB)            // 67584
#define OFF_BHI  (2 * 128 * PITCHB)        // 135168
#define OFF_BLO  (OFF_BHI + 64 * PITCHB)   // 168960
#define ESN_SMEM (OFF_BLO + 64 * PITCHB)   // 202752
// C transpose area reuses BHI region: 64 x 132 floats = 33792 B (exactly BHI size)
#define CPITCHF 132

// ---- device globals ----
__device__ float g_Z[(size_t)TT * BB * RR];     // [t][b][r]
__device__ float g_XT[BB * RR];                 // state [b][r]
__device__ float g_P[KSPLIT][BB * RR];          // split-K partials [s][b][r]
__device__ unsigned int g_flag[128 * 8];        // barrier flags

// =================== helpers ===================
__device__ __forceinline__ uint32_t smem_u32(const void* p) {
    uint32_t a;
    asm("{ .reg .u64 t; cvta.to.shared.u64 t, %1; cvt.u32.u64 %0, t; }" : "=r"(a) : "l"(p));
    return a;
}
__device__ __forceinline__ void ldmatrix_x4(uint32_t& r0, uint32_t& r1,
                                            uint32_t& r2, uint32_t& r3, uint32_t addr) {
    asm volatile("ldmatrix.sync.aligned.m8n8.x4.shared.b16 {%0,%1,%2,%3}, [%4];"
                 : "=r"(r0), "=r"(r1), "=r"(r2), "=r"(r3) : "r"(addr));
}
__device__ __forceinline__ void mma16816(float& d0, float& d1, float& d2, float& d3,
                                         uint32_t a0, uint32_t a1, uint32_t a2, uint32_t a3,
                                         uint32_t b0, uint32_t b1) {
    asm volatile(
        "mma.sync.aligned.m16n8k16.row.col.f32.bf16.bf16.f32 "
        "{%0,%1,%2,%3}, {%4,%5,%6,%7}, {%8,%9}, {%0,%1,%2,%3};"
        : "+f"(d0), "+f"(d1), "+f"(d2), "+f"(d3)
        : "r"(a0), "r"(a1), "r"(a2), "r"(a3), "r"(b0), "r"(b1));
}
// pack fp32 pair -> (hi bf16 x2, lo bf16 x2)
__device__ __forceinline__ void split2(float2 v, uint32_t& hw, uint32_t& lw) {
    __nv_bfloat16 h0 = __float2bfloat16_rn(v.x), h1 = __float2bfloat16_rn(v.y);
    float l0 = v.x - __bfloat162float(h0), l1 = v.y - __bfloat162float(h1);
    __nv_bfloat16 g0 = __float2bfloat16_rn(l0), g1 = __float2bfloat16_rn(l1);
    hw = (uint32_t)__bfloat16_as_ushort(h0) | ((uint32_t)__bfloat16_as_ushort(h1) << 16);
    lw = (uint32_t)__bfloat16_as_ushort(g0) | ((uint32_t)__bfloat16_as_ushort(g1) << 16);
}

// ---- fp32x2 (proj) ----
__device__ __forceinline__ void fma2(unsigned long long& d, unsigned long long a,
                                     unsigned long long b) {
    asm("fma.rn.f32x2 %0, %1, %2, %0;" : "+l"(d) : "l"(a), "l"(b));
}
__device__ __forceinline__ float hsum2(unsigned long long v) {
    float lo, hi;
    asm("mov.b64 {%0, %1}, %2;" : "=f"(lo), "=f"(hi) : "l"(v));
    return lo + hi;
}
__device__ __forceinline__ void cp_async16(void* smem_dst, const void* gsrc) {
    unsigned s = (unsigned)__cvta_generic_to_shared(smem_dst);
    asm volatile("cp.async.cg.shared.global [%0], [%1], 16;" :: "r"(s), "l"(gsrc));
}
__device__ __forceinline__ void cp_commit() { asm volatile("cp.async.commit_group;"); }
template <int N>
__device__ __forceinline__ void cp_wait() {
    asm volatile("cp.async.wait_group %0;" :: "n"(N));
}
__device__ __forceinline__ float4 ldcs4(const float4* p) {
    float4 v;
    asm volatile("ld.global.cs.v4.f32 {%0,%1,%2,%3}, [%4];"
                 : "=f"(v.x), "=f"(v.y), "=f"(v.z), "=f"(v.w) : "l"(p));
    return v;
}

// ---- flag-array grid barrier (128 co-resident CTAs) ----
__device__ __forceinline__ void grid_sync(unsigned phase) {
    __threadfence();
    __syncthreads();
    if (threadIdx.x == 0)
        ((volatile unsigned*)g_flag)[blockIdx.x * 8] = phase;
    if (threadIdx.x < 128) {
        while (((volatile unsigned*)g_flag)[threadIdx.x * 8] < phase) {}
    }
    __threadfence();
    __syncthreads();
}

// ---------------------------------------------------------------------------
__global__ void init_kernel(const float* __restrict__ init) {
    int idx = blockIdx.x * blockDim.x + threadIdx.x;
    g_XT[idx] = init[idx & (RR - 1)];
    if (idx < 128 * 8) g_flag[idx] = 0u;
}

// ---------------------------------------------------------------------------
// proj (fp32 SIMT, validated): Z[t][b][r] = bias[r] + emb[t][b]·w_in[r]
// ---------------------------------------------------------------------------
__device__ __forceinline__ void mma_chunk(const float* __restrict__ Wsb,
                                          const float* __restrict__ Xsb,
                                          int rg, int bg,
                                          unsigned long long acc[4][4]) {
#pragma unroll
    for (int k = 0; k < 64; k += 4) {
        ulonglong2 w[4], x[4];
#pragma unroll
        for (int rr = 0; rr < 4; rr++)
            w[rr] = *(const ulonglong2*)(Wsb + (rr * 16 + rg) * ROWF + k);
#pragma unroll
        for (int bb = 0; bb < 4; bb++)
            x[bb] = *(const ulonglong2*)(Xsb + (bb * 16 + bg) * ROWF + k);
#pragma unroll
        for (int rr = 0; rr < 4; rr++)
#pragma unroll
            for (int bb = 0; bb < 4; bb++) {
                fma2(acc[rr][bb], w[rr].x, x[bb].x);
                fma2(acc[rr][bb], w[rr].y, x[bb].y);
            }
    }
}

__global__ void __launch_bounds__(256)
proj_kernel(const float* __restrict__ emb,
            const float* __restrict__ w_in,
            const float* __restrict__ bias) {
    extern __shared__ float sm[];
    float* Ws[2] = { sm, sm + CHF };
    float* Xs[2] = { sm + 2 * CHF, sm + 3 * CHF };

    const int tid = threadIdx.x;
    const int r0 = blockIdx.x * 64;
    const int t  = blockIdx.y;
    const int rg = tid & 15, bg = tid >> 4;
    const int lrow = tid >> 4, lseg = tid & 15;

    unsigned long long acc[4][4] = {};
    const int NCH = DD / 64;

#pragma unroll
    for (int j = 0; j < 4; j++) {
        int row = lrow + j * 16;
        cp_async16(Ws[0] + row * ROWF + lseg * 4, w_in + (size_t)(r0 + row) * DD + lseg * 4);
        cp_async16(Xs[0] + row * ROWF + lseg * 4, emb + ((size_t)t * 64 + row) * DD + lseg * 4);
    }
    cp_commit();

    int buf = 0;
    for (int c = 0; c < NCH; c++) {
        if (c + 1 < NCH) {
            int kb = (c + 1) * 64;
#pragma unroll
            for (int j = 0; j < 4; j++) {
                int row = lrow + j * 16;
                cp_async16(Ws[buf ^ 1] + row * ROWF + lseg * 4,
                           w_in + (size_t)(r0 + row) * DD + kb + lseg * 4);
                cp_async16(Xs[buf ^ 1] + row * ROWF + lseg * 4,
                           emb + ((size_t)t * 64 + row) * DD + kb + lseg * 4);
            }
            cp_commit();
            cp_wait<1>();
        } else {
            cp_wait<0>();
        }
        __syncthreads();
        mma_chunk(Ws[buf], Xs[buf], rg, bg, acc);
        __syncthreads();
        buf ^= 1;
    }

    float bz[4];
#pragma unroll
    for (int rr = 0; rr < 4; rr++) bz[rr] = bias[r0 + rr * 16 + rg];
#pragma unroll
    for (int bb = 0; bb < 4; bb++) {
        int b = bb * 16 + bg;
        float* z = &g_Z[((size_t)t * BB + b) * RR + r0 + rg];
#pragma unroll
        for (int rr = 0; rr < 4; rr++)
            z[rr * 16] = hsum2(acc[rr][bb]) + bz[rr];
    }
}

// ---------------------------------------------------------------------------
// esn: persistent recurrence on mma.sync (bf16 3-split, fp32 accum).
// 128 CTAs = 16 M-blocks x 8 K-splits; warp w owns rows w*16..w*16+15.
// ---------------------------------------------------------------------------
__global__ void __launch_bounds__(256)
esn_kernel(const int* __restrict__ lengths,
           const float* __restrict__ w_res,
           float* __restrict__ out) {
    extern __shared__ char smem[];
    const uint32_t sbase = smem_u32(smem);
    const int tid = threadIdx.x;
    const int wid = tid >> 5, lane = tid & 31;

    const int rb = blockIdx.x >> 3;          // 0..15 M-block
    const int ks = blockIdx.x & 7;           // 0..7 K-split
    const int r0 = rb * 128;
    const int k0 = ks * KS;

    const int ridx = blockIdx.x * 1024 + tid * 4;   // epilogue ownership on [b][r]
    const int rb_b = ridx >> 11;
    const int rlen = lengths[rb_b];

    // --- convert W_res slice (128 x 256) to bf16 hi/lo, resident in smem ---
    for (int j = 0; j < 64; j++) {
        int lin2 = tid + j * 256;            // 16384 float2
        int r = lin2 >> 7, kk = (lin2 & 127) * 2;
        float2 v = *(const float2*)&w_res[(size_t)(r0 + r) * RR + k0 + kk];
        uint32_t hw, lw;
        split2(v, hw, lw);
        uint32_t boff = r * PITCHB + kk * 2;
        *(uint32_t*)(smem + OFF_WHI + boff) = hw;
        *(uint32_t*)(smem + OFF_WLO + boff) = lw;
    }
    __syncthreads();

    // ldmatrix per-lane address components
    const uint32_t aRowOff = (uint32_t)((wid * 16 + (lane & 15)) * PITCHB + (lane >> 4) * 16);
    const int bq = lane >> 3;                 // 0..3 (x4 quadrant)
    const uint32_t bRowOff = (uint32_t)((((bq >> 1) * 8) + (lane & 7)) * PITCHB + (bq & 1) * 16);

    unsigned phase = 0;

    for (int t = 0; t < TT; t++) {
        // prefetch epilogue operands (stable during this step)
        float4 z4 = ldcs4((const float4*)&g_Z[(size_t)t * (BB * RR) + ridx]);
        float4 xo = *(const float4*)&g_XT[ridx];

        // ---- stage x slice (64 b x 256 k) -> bf16 hi/lo ----
        for (int j = 0; j < 32; j++) {
            int lin2 = tid + j * 256;        // 8192 float2
            int b = lin2 >> 7, kk = (lin2 & 127) * 2;
            float2 v = *(const float2*)&g_XT[b * RR + k0 + kk];
            uint32_t hw, lw;
            split2(v, hw, lw);
            uint32_t boff = b * PITCHB + kk * 2;
            *(uint32_t*)(smem + OFF_BHI + boff) = hw;
            *(uint32_t*)(smem + OFF_BLO + boff) = lw;
        }
        __syncthreads();

        // ---- 3-split mma: acc = Whi*xhi + Whi*xlo + Wlo*xhi ----
        float acc[8][4];
#pragma unroll
        for (int i = 0; i < 8; i++)
#pragma unroll
            for (int q = 0; q < 4; q++) acc[i][q] = 0.0f;

#pragma unroll
        for (int s = 0; s < 3; s++) {
            const uint32_t aBase = sbase + ((s == 2) ? OFF_WLO : OFF_WHI) + aRowOff;
            const uint32_t bBase = sbase + ((s == 1) ? OFF_BLO : OFF_BHI) + bRowOff;
#pragma unroll 4
            for (int kc = 0; kc < 16; kc++) {
                uint32_t a0, a1, a2, a3;
                ldmatrix_x4(a0, a1, a2, a3, aBase + kc * 32);
#pragma unroll
                for (int jp = 0; jp < 4; jp++) {
                    uint32_t b0, b1, b2, b3;
                    ldmatrix_x4(b0, b1, b2, b3, bBase + jp * (16 * PITCHB) + kc * 32);
                    mma16816(acc[jp*2][0], acc[jp*2][1], acc[jp*2][2], acc[jp*2][3],
                             a0, a1, a2, a3, b0, b1);
                    mma16816(acc[jp*2+1][0], acc[jp*2+1][1], acc[jp*2+1][2], acc[jp*2+1][3],
                             a0, a1, a2, a3, b2, b3);
                }
            }
        }
        __syncthreads();   // B buffers dead; reuse BHI as C transpose area

        // ---- transpose C fragments into smem [b][r_local] (pitch 132 f) ----
        {
            float* Csm = (float*)(smem + OFF_BHI);
            const int grp = lane >> 2, qid = lane & 3;
            const int row = wid * 16 + grp;
#pragma unroll
            for (int idx = 0; idx < 8; idx++) {
                int col = idx * 8 + qid * 2;
                Csm[col * CPITCHF + row]           = acc[idx][0];
                Csm[(col + 1) * CPITCHF + row]     = acc[idx][1];
                Csm[col * CPITCHF + row + 8]       = acc[idx][2];
                Csm[(col + 1) * CPITCHF + row + 8] = acc[idx][3];
            }
        }
        __syncthreads();

        // ---- coalesced partial store: g_P[ks][b][r0 + r] ----
        {
            const float* Csm = (const float*)(smem + OFF_BHI);
            const int rr4 = (tid & 31) * 4;
            const int b0 = tid >> 5;          // 0..7
#pragma unroll
            for (int p = 0; p < 8; p++) {
                int b = b0 + p * 8;
                float4 v = *(const float4*)&Csm[b * CPITCHF + rr4];
                *(float4*)&g_P[ks][b * RR + r0 + rr4] = v;
            }
        }

        grid_sync(++phase);

        // ---- reduce + leaky tanh epilogue ----
        {
            float4 s;
            s.x = 0.f; s.y = 0.f; s.z = 0.f; s.w = 0.f;
#pragma unroll
            for (int p = 0; p < KSPLIT; p++) {
                float4 v = *(const float4*)&g_P[p][ridx];
                s.x += v.x; s.y += v.y; s.z += v.z; s.w += v.w;
            }
            float m = (t < rlen) ? 0.5f : 0.0f;
            float4 xn;
            xn.x = m * (xo.x + tanhf(s.x + z4.x));
            xn.y = m * (xo.y + tanhf(s.y + z4.y));
            xn.z = m * (xo.z + tanhf(s.z + z4.z));
            xn.w = m * (xo.w + tanhf(s.w + z4.w));

            *(float4*)&g_XT[ridx] = xn;
            *(float4*)&out[((size_t)rb_b * TT + t) * RR + (ridx & (RR - 1))] = xn;
        }

        grid_sync(++phase);
    }
}

// ---------------------------------------------------------------------------
extern "C" void kernel_launch(void* const* d_in, const int* in_sizes, int n_in,
                              void* d_out, int out_size) {
    const float* emb     = (const float*)d_in[0];
    const int*   lengths = (const int*)  d_in[1];
    const float* w_in    = (const float*)d_in[2];
    const float* w_res   = (const float*)d_in[3];
    const float* bias    = (const float*)d_in[4];
    const float* init    = (const float*)d_in[5];
    float* out = (float*)d_out;

    cudaFuncSetAttribute(proj_kernel, cudaFuncAttributeMaxDynamicSharedMemorySize, PROJ_SMEM);
    cudaFuncSetAttribute(esn_kernel,  cudaFuncAttributeMaxDynamicSharedMemorySize, ESN_SMEM);

    init_kernel<<<(BB * RR) / 256, 256>>>(init);
    proj_kernel<<<dim3(RR / 64, TT), 256, PROJ_SMEM>>>(emb, w_in, bias);
    esn_kernel<<<128, 256, ESN_SMEM>>>(lengths, w_res, out);
}

// round 15
// speedup vs baseline: 4.8952x; 1.3486x over previous
#include <cuda_runtime.h>
#include <cuda_bf16.h>
#include <math.h>
#include <stdint.h>

#define TT 256
#define BB 64
#define DD 768
#define RR 2048
#define KSPLIT 8
#define KS (RR / KSPLIT)          // 256 k per CTA

// ---- esn smem layout (bytes). bf16 rows padded to 528B ----
#define PITCHB 528
#define OFF_WHI  0
#define OFF_WLO  (128 * PITCHB)            // 67584
#define OFF_BHI  (2 * 128 * PITCHB)        // 135168
#define OFF_BLO  (OFF_BHI + 64 * PITCHB)   // 168960
#define ESN_SMEM (OFF_BLO + 64 * PITCHB)   // 202752
#define CPITCHF 132

// ---- proj tensor smem layout: K-chunk = 128 bf16 -> 256B + 16 pad ----
#define PITCH2 272
#define P_AHI 0
#define P_ALO (128 * PITCH2)               // 34816
#define P_BHI (2 * 128 * PITCH2)           // 69632
#define P_BLO (P_BHI + 64 * PITCH2)        // 87040
#define PROJ_SMEM (P_BLO + 64 * PITCH2)    // 104448

// ---- device globals ----
__device__ float g_Z[(size_t)TT * BB * RR];       // [t][b][r]
__device__ float g_XT[BB * RR];                   // state fp32 [b][r]
__device__ uint32_t g_XBH[BB * RR / 2];           // state bf16 hi pairs [b][r/2]
__device__ uint32_t g_XBL[BB * RR / 2];           // state bf16 lo pairs
__device__ uint32_t g_WIH[RR * DD / 2];           // w_in bf16 hi pairs [r][d/2]
__device__ uint32_t g_WIL[RR * DD / 2];
__device__ uint32_t g_EH[(size_t)TT * BB * DD / 2];  // emb bf16 hi pairs [t*64+b][d/2]
__device__ uint32_t g_EL[(size_t)TT * BB * DD / 2];
__device__ float g_P[KSPLIT][BB * RR];            // split-K partials [s][b][r]
__device__ unsigned int g_flag[128 * 8];          // barrier flags

// =================== helpers ===================
__device__ __forceinline__ uint32_t smem_u32(const void* p) {
    uint32_t a;
    asm("{ .reg .u64 t; cvta.to.shared.u64 t, %1; cvt.u32.u64 %0, t; }" : "=r"(a) : "l"(p));
    return a;
}
__device__ __forceinline__ void ldmatrix_x4(uint32_t& r0, uint32_t& r1,
                                            uint32_t& r2, uint32_t& r3, uint32_t addr) {
    asm volatile("ldmatrix.sync.aligned.m8n8.x4.shared.b16 {%0,%1,%2,%3}, [%4];"
                 : "=r"(r0), "=r"(r1), "=r"(r2), "=r"(r3) : "r"(addr));
}
__device__ __forceinline__ void mma16816(float& d0, float& d1, float& d2, float& d3,
                                         uint32_t a0, uint32_t a1, uint32_t a2, uint32_t a3,
                                         uint32_t b0, uint32_t b1) {
    asm volatile(
        "mma.sync.aligned.m16n8k16.row.col.f32.bf16.bf16.f32 "
        "{%0,%1,%2,%3}, {%4,%5,%6,%7}, {%8,%9}, {%0,%1,%2,%3};"
        : "+f"(d0), "+f"(d1), "+f"(d2), "+f"(d3)
        : "r"(a0), "r"(a1), "r"(a2), "r"(a3), "r"(b0), "r"(b1));
}
__device__ __forceinline__ void split2(float2 v, uint32_t& hw, uint32_t& lw) {
    __nv_bfloat16 h0 = __float2bfloat16_rn(v.x), h1 = __float2bfloat16_rn(v.y);
    float l0 = v.x - __bfloat162float(h0), l1 = v.y - __bfloat162float(h1);
    __nv_bfloat16 g0 = __float2bfloat16_rn(l0), g1 = __float2bfloat16_rn(l1);
    hw = (uint32_t)__bfloat16_as_ushort(h0) | ((uint32_t)__bfloat16_as_ushort(h1) << 16);
    lw = (uint32_t)__bfloat16_as_ushort(g0) | ((uint32_t)__bfloat16_as_ushort(g1) << 16);
}
__device__ __forceinline__ void cp_async16(void* smem_dst, const void* gsrc) {
    unsigned s = (unsigned)__cvta_generic_to_shared(smem_dst);
    asm volatile("cp.async.cg.shared.global [%0], [%1], 16;" :: "r"(s), "l"(gsrc));
}
__device__ __forceinline__ void cp_commit() { asm volatile("cp.async.commit_group;"); }
template <int N>
__device__ __forceinline__ void cp_wait() {
    asm volatile("cp.async.wait_group %0;" :: "n"(N));
}
__device__ __forceinline__ float4 ldcs4(const float4* p) {
    float4 v;
    asm volatile("ld.global.cs.v4.f32 {%0,%1,%2,%3}, [%4];"
                 : "=f"(v.x), "=f"(v.y), "=f"(v.z), "=f"(v.w) : "l"(p));
    return v;
}

// ---- flag-array grid barrier (128 co-resident CTAs) ----
__device__ __forceinline__ void grid_sync(unsigned phase) {
    __threadfence();
    __syncthreads();
    if (threadIdx.x == 0)
        ((volatile unsigned*)g_flag)[blockIdx.x * 8] = phase;
    if (threadIdx.x < 128) {
        while (((volatile unsigned*)g_flag)[threadIdx.x * 8] < phase) {}
    }
    __threadfence();
    __syncthreads();
}

// ---------------------------------------------------------------------------
// init: fp32 + bf16 state, barrier flags
// ---------------------------------------------------------------------------
__global__ void init_kernel(const float* __restrict__ init) {
    int i2 = blockIdx.x * blockDim.x + threadIdx.x;   // 0 .. BB*RR/2-1
    int r0 = (2 * i2) & (RR - 1);
    float2 v = make_float2(init[r0], init[r0 + 1]);
    *(float2*)&g_XT[2 * i2] = v;
    uint32_t hw, lw;
    split2(v, hw, lw);
    g_XBH[i2] = hw;
    g_XBL[i2] = lw;
    if (i2 < 128 * 8) g_flag[i2] = 0u;
}

// ---------------------------------------------------------------------------
// conv: fp32 array -> bf16 hi/lo pair arrays (elementwise, grid-stride)
// ---------------------------------------------------------------------------
__global__ void conv_kernel(const float* __restrict__ src,
                            uint32_t* __restrict__ dstH,
                            uint32_t* __restrict__ dstL, int n2) {
    int i = blockIdx.x * blockDim.x + threadIdx.x;
    if (i < n2) {
        float2 v = *(const float2*)&src[2 * i];
        uint32_t hw, lw;
        split2(v, hw, lw);
        dstH[i] = hw;
        dstL[i] = lw;
    }
}

// ---------------------------------------------------------------------------
// proj (tensor): Z[t][b][r] = bias[r] + emb[t*64+b]·w_in[r]
// grid (16 r-blocks, 256 t), 256 thr. Tile 128r x 64n, K=768 in 6 chunks.
// ---------------------------------------------------------------------------
__global__ void __launch_bounds__(256)
proj_kernel(const float* __restrict__ bias, float* __restrict__ zout) {
    extern __shared__ char smem[];
    const uint32_t sbase = smem_u32(smem);
    const int tid = threadIdx.x;
    const int wid = tid >> 5, lane = tid & 31;
    const int r0 = blockIdx.x * 128;
    const int t  = blockIdx.y;

    const int seg = tid & 15, rowb = tid >> 4;

    const uint32_t aRowOff = (uint32_t)((wid * 16 + (lane & 15)) * PITCH2 + (lane >> 4) * 16);
    const int bq = lane >> 3;
    const uint32_t bRowOff = (uint32_t)((((bq >> 1) * 8) + (lane & 7)) * PITCH2 + (bq & 1) * 16);

    float acc[8][4];
#pragma unroll
    for (int i = 0; i < 8; i++)
#pragma unroll
        for (int q = 0; q < 4; q++) acc[i][q] = 0.0f;

    for (int c = 0; c < DD / 128; c++) {
        const int kb = c * 128;
        // ---- load chunk: A (w_in) 128x128 bf16 hi/lo, B (emb) 64x128 hi/lo ----
#pragma unroll
        for (int j = 0; j < 8; j++) {
            int row = rowb + j * 16;
            size_t so = ((size_t)(r0 + row) * DD + kb) * 2 + seg * 16;
            cp_async16(smem + P_AHI + row * PITCH2 + seg * 16, (const char*)g_WIH + so);
            cp_async16(smem + P_ALO + row * PITCH2 + seg * 16, (const char*)g_WIL + so);
        }
#pragma unroll
        for (int j = 0; j < 4; j++) {
            int row = rowb + j * 16;
            size_t so = ((size_t)(t * 64 + row) * DD + kb) * 2 + seg * 16;
            cp_async16(smem + P_BHI + row * PITCH2 + seg * 16, (const char*)g_EH + so);
            cp_async16(smem + P_BLO + row * PITCH2 + seg * 16, (const char*)g_EL + so);
        }
        cp_commit();
        cp_wait<0>();
        __syncthreads();

        // ---- 3-split mma on this chunk ----
#pragma unroll
        for (int s = 0; s < 3; s++) {
            const uint32_t aBase = sbase + ((s == 2) ? P_ALO : P_AHI) + aRowOff;
            const uint32_t bBase = sbase + ((s == 1) ? P_BLO : P_BHI) + bRowOff;
#pragma unroll
            for (int kc = 0; kc < 8; kc++) {
                uint32_t a0, a1, a2, a3;
                ldmatrix_x4(a0, a1, a2, a3, aBase + kc * 32);
#pragma unroll
                for (int jp = 0; jp < 4; jp++) {
                    uint32_t b0, b1, b2, b3;
                    ldmatrix_x4(b0, b1, b2, b3, bBase + jp * (16 * PITCH2) + kc * 32);
                    mma16816(acc[jp*2][0], acc[jp*2][1], acc[jp*2][2], acc[jp*2][3],
                             a0, a1, a2, a3, b0, b1);
                    mma16816(acc[jp*2+1][0], acc[jp*2+1][1], acc[jp*2+1][2], acc[jp*2+1][3],
                             a0, a1, a2, a3, b2, b3);
                }
            }
        }
        __syncthreads();
    }

    // ---- transpose C fragments into smem [n][r_local] ----
    {
        float* Csm = (float*)smem;     // reuse A area (33792 B < 34816)
        const int grp = lane >> 2, qid = lane & 3;
        const int row = wid * 16 + grp;
#pragma unroll
        for (int idx = 0; idx < 8; idx++) {
            int col = idx * 8 + qid * 2;
            Csm[col * CPITCHF + row]           = acc[idx][0];
            Csm[(col + 1) * CPITCHF + row]     = acc[idx][1];
            Csm[col * CPITCHF + row + 8]       = acc[idx][2];
            Csm[(col + 1) * CPITCHF + row + 8] = acc[idx][3];
        }
    }
    __syncthreads();

    // ---- coalesced store with bias: Z[t][b][r0+r] ----
    {
        const float* Csm = (const float*)smem;
        const int rr4 = (tid & 31) * 4;
        const int b0 = tid >> 5;
        float4 bz = *(const float4*)&bias[r0 + rr4];
#pragma unroll
        for (int p = 0; p < 8; p++) {
            int b = b0 + p * 8;
            float4 v = *(const float4*)&Csm[b * CPITCHF + rr4];
            v.x += bz.x; v.y += bz.y; v.z += bz.z; v.w += bz.w;
            *(float4*)&zout[((size_t)t * BB + b) * RR + r0 + rr4] = v;
        }
    }
}

// ---------------------------------------------------------------------------
// esn: persistent recurrence on mma.sync (bf16 3-split, fp32 accum).
// 128 CTAs = 16 M-blocks x 8 K-splits; warp w owns rows w*16..w*16+15.
// ---------------------------------------------------------------------------
__global__ void __launch_bounds__(256)
esn_kernel(const int* __restrict__ lengths,
           const float* __restrict__ w_res,
           float* __restrict__ out) {
    extern __shared__ char smem[];
    const uint32_t sbase = smem_u32(smem);
    const int tid = threadIdx.x;
    const int wid = tid >> 5, lane = tid & 31;

    const int rb = blockIdx.x >> 3;          // 0..15 M-block
    const int ks = blockIdx.x & 7;           // 0..7 K-split
    const int r0 = rb * 128;
    const int k0 = ks * KS;

    const int ridx = blockIdx.x * 1024 + tid * 4;   // epilogue ownership on [b][r]
    const int rb_b = ridx >> 11;
    const int rlen = lengths[rb_b];

    // --- convert W_res slice (128 x 256) to bf16 hi/lo, resident in smem ---
    for (int j = 0; j < 64; j++) {
        int lin2 = tid + j * 256;            // 16384 float2
        int r = lin2 >> 7, kk = (lin2 & 127) * 2;
        float2 v = *(const float2*)&w_res[(size_t)(r0 + r) * RR + k0 + kk];
        uint32_t hw, lw;
        split2(v, hw, lw);
        uint32_t boff = r * PITCHB + kk * 2;
        *(uint32_t*)(smem + OFF_WHI + boff) = hw;
        *(uint32_t*)(smem + OFF_WLO + boff) = lw;
    }
    __syncthreads();

    const uint32_t aRowOff = (uint32_t)((wid * 16 + (lane & 15)) * PITCHB + (lane >> 4) * 16);
    const int bq = lane >> 3;
    const uint32_t bRowOff = (uint32_t)((((bq >> 1) * 8) + (lane & 7)) * PITCHB + (bq & 1) * 16);

    // staging cp.async coords: 2048 16B-segments per buffer, 8 per thread
    const int srow = tid >> 5;               // base row (b)
    const int sseg = tid & 31;               // 16B segment within 512B row

    unsigned phase = 0;

    for (int t = 0; t < TT; t++) {
        // prefetch epilogue operands (stable during this step)
        float4 z4 = ldcs4((const float4*)&g_Z[(size_t)t * (BB * RR) + ridx]);
        float4 xo = *(const float4*)&g_XT[ridx];

        // ---- stage x slice (64 b x 256 k) bf16 hi/lo via cp.async ----
#pragma unroll
        for (int j = 0; j < 8; j++) {
            int b = srow + j * 8;
            size_t so = ((size_t)b * RR + k0) * 2 + sseg * 16;
            cp_async16(smem + OFF_BHI + b * PITCHB + sseg * 16, (const char*)g_XBH + so);
            cp_async16(smem + OFF_BLO + b * PITCHB + sseg * 16, (const char*)g_XBL + so);
        }
        cp_commit();
        cp_wait<0>();
        __syncthreads();

        // ---- 3-split mma: acc = Whi*xhi + Whi*xlo + Wlo*xhi ----
        float acc[8][4];
#pragma unroll
        for (int i = 0; i < 8; i++)
#pragma unroll
            for (int q = 0; q < 4; q++) acc[i][q] = 0.0f;

#pragma unroll
        for (int s = 0; s < 3; s++) {
            const uint32_t aBase = sbase + ((s == 2) ? OFF_WLO : OFF_WHI) + aRowOff;
            const uint32_t bBase = sbase + ((s == 1) ? OFF_BLO : OFF_BHI) + bRowOff;
#pragma unroll 4
            for (int kc = 0; kc < 16; kc++) {
                uint32_t a0, a1, a2, a3;
                ldmatrix_x4(a0, a1, a2, a3, aBase + kc * 32);
#pragma unroll
                for (int jp = 0; jp < 4; jp++) {
                    uint32_t b0, b1, b2, b3;
                    ldmatrix_x4(b0, b1, b2, b3, bBase + jp * (16 * PITCHB) + kc * 32);
                    mma16816(acc[jp*2][0], acc[jp*2][1], acc[jp*2][2], acc[jp*2][3],
                             a0, a1, a2, a3, b0, b1);
                    mma16816(acc[jp*2+1][0], acc[jp*2+1][1], acc[jp*2+1][2], acc[jp*2+1][3],
                             a0, a1, a2, a3, b2, b3);
                }
            }
        }
        __syncthreads();   // B buffers dead; reuse BHI as C transpose area

        // ---- transpose C fragments into smem [b][r_local] ----
        {
            float* Csm = (float*)(smem + OFF_BHI);
            const int grp = lane >> 2, qid = lane & 3;
            const int row = wid * 16 + grp;
#pragma unroll
            for (int idx = 0; idx < 8; idx++) {
                int col = idx * 8 + qid * 2;
                Csm[col * CPITCHF + row]           = acc[idx][0];
                Csm[(col + 1) * CPITCHF + row]     = acc[idx][1];
                Csm[col * CPITCHF + row + 8]       = acc[idx][2];
                Csm[(col + 1) * CPITCHF + row + 8] = acc[idx][3];
            }
        }
        __syncthreads();

        // ---- coalesced partial store: g_P[ks][b][r0 + r] ----
        {
            const float* Csm = (const float*)(smem + OFF_BHI);
            const int rr4 = (tid & 31) * 4;
            const int b0 = tid >> 5;
#pragma unroll
            for (int p = 0; p < 8; p++) {
                int b = b0 + p * 8;
                float4 v = *(const float4*)&Csm[b * CPITCHF + rr4];
                *(float4*)&g_P[ks][b * RR + r0 + rr4] = v;
            }
        }

        grid_sync(++phase);

        // ---- reduce + leaky tanh epilogue (writes fp32 + bf16 state) ----
        {
            float4 s;
            s.x = 0.f; s.y = 0.f; s.z = 0.f; s.w = 0.f;
#pragma unroll
            for (int p = 0; p < KSPLIT; p++) {
                float4 v = *(const float4*)&g_P[p][ridx];
                s.x += v.x; s.y += v.y; s.z += v.z; s.w += v.w;
            }
            float m = (t < rlen) ? 0.5f : 0.0f;
            float4 xn;
            xn.x = m * (xo.x + tanhf(s.x + z4.x));
            xn.y = m * (xo.y + tanhf(s.y + z4.y));
            xn.z = m * (xo.z + tanhf(s.z + z4.z));
            xn.w = m * (xo.w + tanhf(s.w + z4.w));

            *(float4*)&g_XT[ridx] = xn;
            uint32_t h0, l0, h1, l1;
            split2(make_float2(xn.x, xn.y), h0, l0);
            split2(make_float2(xn.z, xn.w), h1, l1);
            *(uint2*)&g_XBH[ridx >> 1] = make_uint2(h0, h1);
            *(uint2*)&g_XBL[ridx >> 1] = make_uint2(l0, l1);
            *(float4*)&out[((size_t)rb_b * TT + t) * RR + (ridx & (RR - 1))] = xn;
        }

        grid_sync(++phase);
    }
}

// ---------------------------------------------------------------------------
extern "C" void kernel_launch(void* const* d_in, const int* in_sizes, int n_in,
                              void* d_out, int out_size) {
    const float* emb     = (const float*)d_in[0];
    const int*   lengths = (const int*)  d_in[1];
    const float* w_in    = (const float*)d_in[2];
    const float* w_res   = (const float*)d_in[3];
    const float* bias    = (const float*)d_in[4];
    const float* init    = (const float*)d_in[5];
    float* out = (float*)d_out;

    cudaFuncSetAttribute(proj_kernel, cudaFuncAttributeMaxDynamicSharedMemorySize, PROJ_SMEM);
    cudaFuncSetAttribute(esn_kernel,  cudaFuncAttributeMaxDynamicSharedMemorySize, ESN_SMEM);

    init_kernel<<<(BB * RR / 2) / 256, 256>>>(init);

    uint32_t *wih, *wil, *eh, *el;
    cudaGetSymbolAddress((void**)&wih, g_WIH);
    cudaGetSymbolAddress((void**)&wil, g_WIL);
    cudaGetSymbolAddress((void**)&eh,  g_EH);
    cudaGetSymbolAddress((void**)&el,  g_EL);
    conv_kernel<<<(RR * DD / 2) / 256, 256>>>(w_in, wih, wil, RR * DD / 2);
    conv_kernel<<<((int)((size_t)TT * BB * DD / 2)) / 256, 256>>>(
        emb, eh, el, (int)((size_t)TT * BB * DD / 2));

    float* zp;
    cudaGetSymbolAddress((void**)&zp, g_Z);
    proj_kernel<<<dim3(RR / 128, TT), 256, PROJ_SMEM>>>(bias, zp);
    esn_kernel<<<128, 256, ESN_SMEM>>>(lengths, w_res, out);
}

// round 17
// speedup vs baseline: 5.1538x; 1.0528x over previous
#include <cuda_runtime.h>
#include <cuda_bf16.h>
#include <math.h>
#include <stdint.h>

#define TT 256
#define BB 64
#define DD 768
#define RR 2048
#define KSPLIT 8
#define KS (RR / KSPLIT)          // 256 k per CTA

// ---- esn smem layout (bytes). bf16 rows padded to 528B ----
#define PITCHB 528
#define OFF_WHI  0
#define OFF_WLO  (128 * PITCHB)            // 67584
#define OFF_BHI  (2 * 128 * PITCHB)        // 135168
#define OFF_BLO  (OFF_BHI + 64 * PITCHB)   // 168960
#define ESN_SMEM (OFF_BLO + 64 * PITCHB)   // 202752
#define CPITCHF 132

// ---- proj tensor smem layout: K-chunk = 128 bf16 -> 256B + 16 pad ----
#define PITCH2 272
#define P_AHI 0
#define P_ALO (128 * PITCH2)               // 34816
#define P_BHI (2 * 128 * PITCH2)           // 69632
#define P_BLO (P_BHI + 64 * PITCH2)        // 87040
#define PROJ_STAGE (P_BLO + 64 * PITCH2)   // 104448 per stage
#define PROJ_SMEM (2 * PROJ_STAGE)         // 208896 (double-buffered)

// ---- device globals ----
__device__ float g_Z[(size_t)TT * BB * RR];       // [t][b][r]
__device__ float g_XT[BB * RR];                   // state fp32 [b][r]
__device__ uint32_t g_XBH[BB * RR / 2];           // state bf16 hi pairs [b][r/2]
__device__ uint32_t g_XBL[BB * RR / 2];           // state bf16 lo pairs
__device__ uint32_t g_WIH[RR * DD / 2];           // w_in bf16 hi pairs [r][d/2]
__device__ uint32_t g_WIL[RR * DD / 2];
__device__ uint32_t g_EH[(size_t)TT * BB * DD / 2];  // emb bf16 hi pairs
__device__ uint32_t g_EL[(size_t)TT * BB * DD / 2];
__device__ float g_P[KSPLIT][BB * RR];            // split-K partials [s][b][r]
__device__ unsigned int g_flag[128 * 8];          // barrier flags

// =================== helpers ===================
__device__ __forceinline__ uint32_t smem_u32(const void* p) {
    uint32_t a;
    asm("{ .reg .u64 t; cvta.to.shared.u64 t, %1; cvt.u32.u64 %0, t; }" : "=r"(a) : "l"(p));
    return a;
}
__device__ __forceinline__ void ldmatrix_x4(uint32_t& r0, uint32_t& r1,
                                            uint32_t& r2, uint32_t& r3, uint32_t addr) {
    asm volatile("ldmatrix.sync.aligned.m8n8.x4.shared.b16 {%0,%1,%2,%3}, [%4];"
                 : "=r"(r0), "=r"(r1), "=r"(r2), "=r"(r3) : "r"(addr));
}
__device__ __forceinline__ void mma16816(float& d0, float& d1, float& d2, float& d3,
                                         uint32_t a0, uint32_t a1, uint32_t a2, uint32_t a3,
                                         uint32_t b0, uint32_t b1) {
    asm volatile(
        "mma.sync.aligned.m16n8k16.row.col.f32.bf16.bf16.f32 "
        "{%0,%1,%2,%3}, {%4,%5,%6,%7}, {%8,%9}, {%0,%1,%2,%3};"
        : "+f"(d0), "+f"(d1), "+f"(d2), "+f"(d3)
        : "r"(a0), "r"(a1), "r"(a2), "r"(a3), "r"(b0), "r"(b1));
}
__device__ __forceinline__ void split2(float2 v, uint32_t& hw, uint32_t& lw) {
    __nv_bfloat16 h0 = __float2bfloat16_rn(v.x), h1 = __float2bfloat16_rn(v.y);
    float l0 = v.x - __bfloat162float(h0), l1 = v.y - __bfloat162float(h1);
    __nv_bfloat16 g0 = __float2bfloat16_rn(l0), g1 = __float2bfloat16_rn(l1);
    hw = (uint32_t)__bfloat16_as_ushort(h0) | ((uint32_t)__bfloat16_as_ushort(h1) << 16);
    lw = (uint32_t)__bfloat16_as_ushort(g0) | ((uint32_t)__bfloat16_as_ushort(g1) << 16);
}
__device__ __forceinline__ void cp_async16(void* smem_dst, const void* gsrc) {
    unsigned s = (unsigned)__cvta_generic_to_shared(smem_dst);
    asm volatile("cp.async.cg.shared.global [%0], [%1], 16;" :: "r"(s), "l"(gsrc));
}
__device__ __forceinline__ void cp_commit() { asm volatile("cp.async.commit_group;"); }
template <int N>
__device__ __forceinline__ void cp_wait() {
    asm volatile("cp.async.wait_group %0;" :: "n"(N));
}
__device__ __forceinline__ float4 ldcs4(const float4* p) {
    float4 v;
    asm volatile("ld.global.cs.v4.f32 {%0,%1,%2,%3}, [%4];"
                 : "=f"(v.x), "=f"(v.y), "=f"(v.z), "=f"(v.w) : "l"(p));
    return v;
}

// ---- flag-array grid barrier (128 co-resident CTAs) ----
__device__ __forceinline__ void grid_sync(unsigned phase) {
    __threadfence();
    __syncthreads();
    if (threadIdx.x == 0)
        ((volatile unsigned*)g_flag)[blockIdx.x * 8] = phase;
    if (threadIdx.x < 128) {
        while (((volatile unsigned*)g_flag)[threadIdx.x * 8] < phase) {}
    }
    __threadfence();
    __syncthreads();
}

// ---------------------------------------------------------------------------
__global__ void init_kernel(const float* __restrict__ init) {
    int i2 = blockIdx.x * blockDim.x + threadIdx.x;   // 0 .. BB*RR/2-1
    int r0 = (2 * i2) & (RR - 1);
    float2 v = make_float2(init[r0], init[r0 + 1]);
    *(float2*)&g_XT[2 * i2] = v;
    uint32_t hw, lw;
    split2(v, hw, lw);
    g_XBH[i2] = hw;
    g_XBL[i2] = lw;
    if (i2 < 128 * 8) g_flag[i2] = 0u;
}

// ---------------------------------------------------------------------------
__global__ void conv_kernel(const float* __restrict__ src,
                            uint32_t* __restrict__ dstH,
                            uint32_t* __restrict__ dstL, int n2) {
    int i = blockIdx.x * blockDim.x + threadIdx.x;
    if (i < n2) {
        float2 v = *(const float2*)&src[2 * i];
        uint32_t hw, lw;
        split2(v, hw, lw);
        dstH[i] = hw;
        dstL[i] = lw;
    }
}

// ---------------------------------------------------------------------------
// proj (tensor, 2-stage pipelined): Z[t][b][r] = bias[r] + emb[t*64+b]·w_in[r]
// grid (16 r-blocks, 256 t), 256 thr. Tile 128r x 64n, K=768 in 6 chunks.
// ---------------------------------------------------------------------------
__global__ void __launch_bounds__(256)
proj_kernel(const float* __restrict__ bias, float* __restrict__ zout) {
    extern __shared__ char smem[];
    const uint32_t sbase = smem_u32(smem);
    const int tid = threadIdx.x;
    const int wid = tid >> 5, lane = tid & 31;
    const int r0 = blockIdx.x * 128;
    const int t  = blockIdx.y;

    const int seg = tid & 15, rowb = tid >> 4;

    const uint32_t aRowOff = (uint32_t)((wid * 16 + (lane & 15)) * PITCH2 + (lane >> 4) * 16);
    const int bq = lane >> 3;
    const uint32_t bRowOff = (uint32_t)((((bq >> 1) * 8) + (lane & 7)) * PITCH2 + (bq & 1) * 16);

    float acc[8][4];
#pragma unroll
    for (int i = 0; i < 8; i++)
#pragma unroll
        for (int q = 0; q < 4; q++) acc[i][q] = 0.0f;

    const int NCH = DD / 128;   // 6

    // ---- chunk loader into stage sb ----
    auto load_chunk = [&](int c, int sb) {
        const int kb = c * 128;
        char* base = smem + sb * PROJ_STAGE;
#pragma unroll
        for (int j = 0; j < 8; j++) {
            int row = rowb + j * 16;
            size_t so = ((size_t)(r0 + row) * DD + kb) * 2 + seg * 16;
            cp_async16(base + P_AHI + row * PITCH2 + seg * 16, (const char*)g_WIH + so);
            cp_async16(base + P_ALO + row * PITCH2 + seg * 16, (const char*)g_WIL + so);
        }
#pragma unroll
        for (int j = 0; j < 4; j++) {
            int row = rowb + j * 16;
            size_t so = ((size_t)(t * 64 + row) * DD + kb) * 2 + seg * 16;
            cp_async16(base + P_BHI + row * PITCH2 + seg * 16, (const char*)g_EH + so);
            cp_async16(base + P_BLO + row * PITCH2 + seg * 16, (const char*)g_EL + so);
        }
    };

    load_chunk(0, 0);
    cp_commit();

    int buf = 0;
    for (int c = 0; c < NCH; c++) {
        if (c + 1 < NCH) {
            load_chunk(c + 1, buf ^ 1);
            cp_commit();
            cp_wait<1>();
        } else {
            cp_wait<0>();
        }
        __syncthreads();

        const uint32_t bb = sbase + buf * PROJ_STAGE;
#pragma unroll
        for (int s = 0; s < 3; s++) {
            const uint32_t aBase = bb + ((s == 2) ? P_ALO : P_AHI) + aRowOff;
            const uint32_t bBase = bb + ((s == 1) ? P_BLO : P_BHI) + bRowOff;
#pragma unroll
            for (int kc = 0; kc < 8; kc++) {
                uint32_t a0, a1, a2, a3;
                ldmatrix_x4(a0, a1, a2, a3, aBase + kc * 32);
#pragma unroll
                for (int jp = 0; jp < 4; jp++) {
                    uint32_t b0, b1, b2, b3;
                    ldmatrix_x4(b0, b1, b2, b3, bBase + jp * (16 * PITCH2) + kc * 32);
                    mma16816(acc[jp*2][0], acc[jp*2][1], acc[jp*2][2], acc[jp*2][3],
                             a0, a1, a2, a3, b0, b1);
                    mma16816(acc[jp*2+1][0], acc[jp*2+1][1], acc[jp*2+1][2], acc[jp*2+1][3],
                             a0, a1, a2, a3, b2, b3);
                }
            }
        }
        __syncthreads();
        buf ^= 1;
    }

    // ---- transpose C fragments into smem [n][r_local] (stage-0 area) ----
    {
        float* Csm = (float*)smem;
        const int grp = lane >> 2, qid = lane & 3;
        const int row = wid * 16 + grp;
#pragma unroll
        for (int idx = 0; idx < 8; idx++) {
            int col = idx * 8 + qid * 2;
            Csm[col * CPITCHF + row]           = acc[idx][0];
            Csm[(col + 1) * CPITCHF + row]     = acc[idx][1];
            Csm[col * CPITCHF + row + 8]       = acc[idx][2];
            Csm[(col + 1) * CPITCHF + row + 8] = acc[idx][3];
        }
    }
    __syncthreads();

    // ---- coalesced store with bias: Z[t][b][r0+r] ----
    {
        const float* Csm = (const float*)smem;
        const int rr4 = (tid & 31) * 4;
        const int b0 = tid >> 5;
        float4 bz = *(const float4*)&bias[r0 + rr4];
#pragma unroll
        for (int p = 0; p < 8; p++) {
            int b = b0 + p * 8;
            float4 v = *(const float4*)&Csm[b * CPITCHF + rr4];
            v.x += bz.x; v.y += bz.y; v.z += bz.z; v.w += bz.w;
            *(float4*)&zout[((size_t)t * BB + b) * RR + r0 + rr4] = v;
        }
    }
}

// ---------------------------------------------------------------------------
// esn: persistent recurrence on mma.sync (bf16 3-split, fp32 accum).
// 128 CTAs = 16 M-blocks x 8 K-splits; staging pipelined in 4 x 64-k chunks.
// ---------------------------------------------------------------------------
__global__ void __launch_bounds__(256)
esn_kernel(const int* __restrict__ lengths,
           const float* __restrict__ w_res,
           float* __restrict__ out) {
    extern __shared__ char smem[];
    const uint32_t sbase = smem_u32(smem);
    const int tid = threadIdx.x;
    const int wid = tid >> 5, lane = tid & 31;

    const int rb = blockIdx.x >> 3;          // 0..15 M-block
    const int ks = blockIdx.x & 7;           // 0..7 K-split
    const int r0 = rb * 128;
    const int k0 = ks * KS;

    const int ridx = blockIdx.x * 1024 + tid * 4;   // epilogue ownership on [b][r]
    const int rb_b = ridx >> 11;
    const int rlen = lengths[rb_b];

    // --- convert W_res slice (128 x 256) to bf16 hi/lo, resident in smem ---
    for (int j = 0; j < 64; j++) {
        int lin2 = tid + j * 256;            // 16384 float2
        int r = lin2 >> 7, kk = (lin2 & 127) * 2;
        float2 v = *(const float2*)&w_res[(size_t)(r0 + r) * RR + k0 + kk];
        uint32_t hw, lw;
        split2(v, hw, lw);
        uint32_t boff = r * PITCHB + kk * 2;
        *(uint32_t*)(smem + OFF_WHI + boff) = hw;
        *(uint32_t*)(smem + OFF_WLO + boff) = lw;
    }
    __syncthreads();

    const uint32_t aRowOff = (uint32_t)((wid * 16 + (lane & 15)) * PITCHB + (lane >> 4) * 16);
    const int bq = lane >> 3;
    const uint32_t bRowOff = (uint32_t)((((bq >> 1) * 8) + (lane & 7)) * PITCHB + (bq & 1) * 16);

    unsigned phase = 0;

    for (int t = 0; t < TT; t++) {
        // prefetch epilogue operands (stable during this step)
        float4 z4 = ldcs4((const float4*)&g_Z[(size_t)t * (BB * RR) + ridx]);
        float4 xo = *(const float4*)&g_XT[ridx];

        // ---- stage x slice as 4 x 64-k chunk groups (pipelined vs MMA) ----
#pragma unroll
        for (int ph = 0; ph < 4; ph++) {
#pragma unroll
            for (int j = 0; j < 2; j++) {
                int sg = tid + j * 256;          // 0..511 segs per buffer-chunk
                int b = sg >> 3;                 // row
                int s16 = sg & 7;                // 16B seg within 128B chunk-row
                size_t go = ((size_t)b * RR + k0 + ph * 64) * 2 + s16 * 16;
                uint32_t so = b * PITCHB + ph * 128 + s16 * 16;
                cp_async16(smem + OFF_BHI + so, (const char*)g_XBH + go);
                cp_async16(smem + OFF_BLO + so, (const char*)g_XBL + go);
            }
            cp_commit();
        }

        // ---- 3-split mma, chunk-outer (consume chunk ph as it lands) ----
        float acc[8][4];
#pragma unroll
        for (int i = 0; i < 8; i++)
#pragma unroll
            for (int q = 0; q < 4; q++) acc[i][q] = 0.0f;

#pragma unroll
        for (int ph = 0; ph < 4; ph++) {
            if (ph == 0)      cp_wait<3>();
            else if (ph == 1) cp_wait<2>();
            else if (ph == 2) cp_wait<1>();
            else              cp_wait<0>();
            __syncthreads();
#pragma unroll
            for (int s = 0; s < 3; s++) {
                const uint32_t aBase = sbase + ((s == 2) ? OFF_WLO : OFF_WHI) + aRowOff;
                const uint32_t bBase = sbase + ((s == 1) ? OFF_BLO : OFF_BHI) + bRowOff;
#pragma unroll
                for (int i = 0; i < 4; i++) {
                    int kc = ph * 4 + i;
                    uint32_t a0, a1, a2, a3;
                    ldmatrix_x4(a0, a1, a2, a3, aBase + kc * 32);
#pragma unroll
                    for (int jp = 0; jp < 4; jp++) {
                        uint32_t b0, b1, b2, b3;
                        ldmatrix_x4(b0, b1, b2, b3, bBase + jp * (16 * PITCHB) + kc * 32);
                        mma16816(acc[jp*2][0], acc[jp*2][1], acc[jp*2][2], acc[jp*2][3],
                                 a0, a1, a2, a3, b0, b1);
                        mma16816(acc[jp*2+1][0], acc[jp*2+1][1], acc[jp*2+1][2], acc[jp*2+1][3],
                                 a0, a1, a2, a3, b2, b3);
                    }
                }
            }
        }
        __syncthreads();   // B buffers dead; reuse BHI as C transpose area

        // ---- transpose C fragments into smem [b][r_local] ----
        {
            float* Csm = (float*)(smem + OFF_BHI);
            const int grp = lane >> 2, qid = lane & 3;
            const int row = wid * 16 + grp;
#pragma unroll
            for (int idx = 0; idx < 8; idx++) {
                int col = idx * 8 + qid * 2;
                Csm[col * CPITCHF + row]           = acc[idx][0];
                Csm[(col + 1) * CPITCHF + row]     = acc[idx][1];
                Csm[col * CPITCHF + row + 8]       = acc[idx][2];
                Csm[(col + 1) * CPITCHF + row + 8] = acc[idx][3];
            }
        }
        __syncthreads();

        // ---- coalesced partial store: g_P[ks][b][r0 + r] ----
        {
            const float* Csm = (const float*)(smem + OFF_BHI);
            const int rr4 = (tid & 31) * 4;
            const int b0 = tid >> 5;
#pragma unroll
            for (int p = 0; p < 8; p++) {
                int b = b0 + p * 8;
                float4 v = *(const float4*)&Csm[b * CPITCHF + rr4];
                *(float4*)&g_P[ks][b * RR + r0 + rr4] = v;
            }
        }

        grid_sync(++phase);

        // ---- reduce + leaky tanh epilogue (writes fp32 + bf16 state) ----
        {
            float4 s;
            s.x = 0.f; s.y = 0.f; s.z = 0.f; s.w = 0.f;
#pragma unroll
            for (int p = 0; p < KSPLIT; p++) {
                float4 v = *(const float4*)&g_P[p][ridx];
                s.x += v.x; s.y += v.y; s.z += v.z; s.w += v.w;
            }
            float m = (t < rlen) ? 0.5f : 0.0f;
            float4 xn;
            xn.x = m * (xo.x + tanhf(s.x + z4.x));
            xn.y = m * (xo.y + tanhf(s.y + z4.y));
            xn.z = m * (xo.z + tanhf(s.z + z4.z));
            xn.w = m * (xo.w + tanhf(s.w + z4.w));

            *(float4*)&g_XT[ridx] = xn;
            uint32_t h0, l0, h1, l1;
            split2(make_float2(xn.x, xn.y), h0, l0);
            split2(make_float2(xn.z, xn.w), h1, l1);
            *(uint2*)&g_XBH[ridx >> 1] = make_uint2(h0, h1);
            *(uint2*)&g_XBL[ridx >> 1] = make_uint2(l0, l1);
            *(float4*)&out[((size_t)rb_b * TT + t) * RR + (ridx & (RR - 1))] = xn;
        }

        grid_sync(++phase);
    }
}

// ---------------------------------------------------------------------------
extern "C" void kernel_launch(void* const* d_in, const int* in_sizes, int n_in,
                              void* d_out, int out_size) {
    const float* emb     = (const float*)d_in[0];
    const int*   lengths = (const int*)  d_in[1];
    const float* w_in    = (const float*)d_in[2];
    const float* w_res   = (const float*)d_in[3];
    const float* bias    = (const float*)d_in[4];
    const float* init    = (const float*)d_in[5];
    float* out = (float*)d_out;

    cudaFuncSetAttribute(proj_kernel, cudaFuncAttributeMaxDynamicSharedMemorySize, PROJ_SMEM);
    cudaFuncSetAttribute(esn_kernel,  cudaFuncAttributeMaxDynamicSharedMemorySize, ESN_SMEM);

    init_kernel<<<(BB * RR / 2) / 256, 256>>>(init);

    uint32_t *wih, *wil, *eh, *el;
    cudaGetSymbolAddress((void**)&wih, g_WIH);
    cudaGetSymbolAddress((void**)&wil, g_WIL);
    cudaGetSymbolAddress((void**)&eh,  g_EH);
    cudaGetSymbolAddress((void**)&el,  g_EL);
    conv_kernel<<<(RR * DD / 2) / 256, 256>>>(w_in, wih, wil, RR * DD / 2);
    conv_kernel<<<((int)((size_t)TT * BB * DD / 2)) / 256, 256>>>(
        emb, eh, el, (int)((size_t)TT * BB * DD / 2));

    float* zp;
    cudaGetSymbolAddress((void**)&zp, g_Z);
    proj_kernel<<<dim3(RR / 128, TT), 256, PROJ_SMEM>>>(bias, zp);
    esn_kernel<<<128, 256, ESN_SMEM>>>(lengths, w_res, out);
}